// round 1
// baseline (speedup 1.0000x reference)
#include <cuda_runtime.h>

#define NN 1024
#define CCH 128
#define MAXB 320

// ---------------- scratch (device globals; no allocation) ----------------
__device__ int   g_bs[NN], g_be[NN];
__device__ float g_qin[NN*CCH], g_kin[NN*CCH];
__device__ float g_q[NN*CCH],  g_k[NN*CCH];
__device__ float g_wt[8*CCH*CCH];      // transposed weights: 0 qw, 1 kw, 2-4 vw[l], 5-7 ow[l]
__device__ float g_V [NN*9*CCH];
__device__ float g_O1[NN*9*CCH];
__device__ float g_O2[NN*9*CCH];

__device__ __forceinline__ float wredsum(float v){
  #pragma unroll
  for(int o=16;o;o>>=1) v += __shfl_xor_sync(0xffffffffu, v, o);
  return v;
}
__device__ __forceinline__ float wredmax(float v){
  #pragma unroll
  for(int o=16;o;o>>=1) v = fmaxf(v, __shfl_xor_sync(0xffffffffu, v, o));
  return v;
}

// SH constants
#define SH_C0 0.28209479177387814f
#define SH_C1 0.4886025119029199f
#define SH_S15 1.0925484305920792f
#define SH_S5 0.6307831305050401f

// ---------------- batch ranges (auto-detect int32 vs int64 batch) ----------------
__global__ void k_batchrange(const int* __restrict__ words){
  __shared__ int mono;
  __shared__ int sb[NN];
  int t = threadIdx.x;
  if(t==0) mono = 1;
  __syncthreads();
  // If buffer is int32, the 1024 words are sorted nondecreasing.
  // If int64 (little-endian values 0..15), words alternate value,0,value,0 -> not monotonic.
  if(t < NN-1 && words[t] > words[t+1]) atomicExch(&mono, 0);
  __syncthreads();
  int b = mono ? words[t] : words[2*t];
  sb[t] = b;
  __syncthreads();
  int lo=0, hi=NN;
  while(lo<hi){ int mid=(lo+hi)>>1; if(sb[mid] <  b) lo=mid+1; else hi=mid; }
  g_bs[t]=lo;
  lo=t; hi=NN;
  while(lo<hi){ int mid=(lo+hi)>>1; if(sb[mid] <= b) lo=mid+1; else hi=mid; }
  g_be[t]=lo;
}

// ---------------- weight transposes: g_wt[m][k*C+c] = W[c*C+k] ----------------
__global__ void k_transpose(const float* __restrict__ qw, const float* __restrict__ kw,
                            const float* __restrict__ vw, const float* __restrict__ ow){
  int mat  = blockIdx.x >> 4;
  int tile = blockIdx.x & 15;
  const float* src;
  if(mat==0) src=qw; else if(mat==1) src=kw;
  else if(mat<5) src=vw + (mat-2)*CCH*CCH;
  else src=ow + (mat-5)*CCH*CCH;
  float* dst = g_wt + mat*CCH*CCH;
  int tx=threadIdx.x, ty=threadIdx.y;
  int bx=(tile&3)*32, by=(tile>>2)*32;
  __shared__ float s[32][33];
  #pragma unroll
  for(int r=0;r<32;r+=8) s[ty+r][tx] = src[(by+ty+r)*CCH + bx+tx];
  __syncthreads();
  #pragma unroll
  for(int r=0;r<32;r+=8) dst[(bx+ty+r)*CCH + by+tx] = s[tx][ty+r];
}

// ---------------- q_in: A[i,m] then q_in[i,c] ----------------
__global__ void __launch_bounds__(256) k_qin(const float* __restrict__ pos,
                                             const float* __restrict__ xemb){
  int i    = blockIdx.x*8 + (threadIdx.x>>5);
  int lane = threadIdx.x & 31;
  float px=pos[i*3+0], py=pos[i*3+1], pz=pos[i*3+2];
  int bs=g_bs[i], be=g_be[i];
  float a0=0,a1=0,a2=0,a3=0,a4=0,a5=0,a6=0,a7=0,a8=0;
  for(int j=bs+lane; j<be; j+=32){
    if(j==i) continue;
    float dx=px-pos[j*3+0], dy=py-pos[j*3+1], dz=pz-pos[j*3+2];
    float d = fmaxf(sqrtf(dx*dx+dy*dy+dz*dz), 1e-8f);
    float inv = 1.0f/d;
    float x=dx*inv, y=dy*inv, z=dz*inv;
    a0 += 1.0f;
    a1 += x; a2 += y; a3 += z;
    a4 += x*z; a5 += x*y;
    a6 += y*y - 0.5f*(x*x+z*z);
    a7 += y*z; a8 += z*z - x*x;
  }
  a0=wredsum(a0); a1=wredsum(a1); a2=wredsum(a2); a3=wredsum(a3);
  a4=wredsum(a4); a5=wredsum(a5); a6=wredsum(a6); a7=wredsum(a7); a8=wredsum(a8);
  const float invN = 1.0f/(float)NN;
  float s0 = a0 * (SH_C0*invN);
  float w1 = SH_C1*invN/3.0f;
  float s1 = a1*w1, s2 = a2*w1, s3 = a3*w1;
  float wa = SH_S15*invN/5.0f, wb = SH_S5*invN/5.0f, wc = 0.5f*SH_S15*invN/5.0f;
  float s4 = a4*wa, s5 = a5*wa, s6 = a6*wb, s7 = a7*wa, s8 = a8*wc;
  const float* xr = xemb + (size_t)i*9*CCH;
  for(int c=lane; c<CCH; c+=32){
    float s = s0*xr[c]       + s1*xr[CCH+c]   + s2*xr[2*CCH+c]
            + s3*xr[3*CCH+c] + s4*xr[4*CCH+c] + s5*xr[5*CCH+c]
            + s6*xr[6*CCH+c] + s7*xr[7*CCH+c] + s8*xr[8*CCH+c];
    g_qin[i*CCH+c] = s;
  }
}

// ---------------- k_in: 4 j's per block, tile i, share x_emb loads ----------------
__global__ void __launch_bounds__(128) k_kin(const float* __restrict__ pos,
                                             const float* __restrict__ xemb){
  const int j0 = blockIdx.x*4;
  const int t  = threadIdx.x;
  __shared__ float ssh[64][4][10];
  __shared__ float spj[4][3];
  __shared__ int   sbsj[4];
  __shared__ int   srange[2];
  if(t<4){
    spj[t][0]=pos[(j0+t)*3+0]; spj[t][1]=pos[(j0+t)*3+1]; spj[t][2]=pos[(j0+t)*3+2];
    sbsj[t]=g_bs[j0+t];
  }
  if(t==0){
    int u0=g_bs[j0], u1=g_be[j0];
    #pragma unroll
    for(int q=1;q<4;q++){ u0=min(u0,g_bs[j0+q]); u1=max(u1,g_be[j0+q]); }
    srange[0]=u0; srange[1]=u1;
  }
  __syncthreads();
  const int u0=srange[0], u1=srange[1];
  const float invN = 1.0f/(float)NN;
  const float w0 = SH_C0*invN;
  const float w1 = SH_C1*invN/3.0f;
  const float wa = SH_S15*invN/5.0f, wb = SH_S5*invN/5.0f, wc = 0.5f*SH_S15*invN/5.0f;
  float acc0=0, acc1=0, acc2=0, acc3=0;
  for(int ib=u0; ib<u1; ib+=64){
    __syncthreads();
    for(int e=t; e<256; e+=128){
      int ii=e>>2, jt=e&3;
      int i = ib+ii;
      float* sp = &ssh[ii][jt][0];
      bool ok = (i<u1) && (i != j0+jt) && (g_bs[i]==sbsj[jt]);
      if(!ok){
        #pragma unroll
        for(int m=0;m<9;m++) sp[m]=0.0f;
      } else {
        float dx=pos[i*3+0]-spj[jt][0];
        float dy=pos[i*3+1]-spj[jt][1];
        float dz=pos[i*3+2]-spj[jt][2];
        float d = fmaxf(sqrtf(dx*dx+dy*dy+dz*dz), 1e-8f);
        float inv = 1.0f/d;
        float x=dx*inv, y=dy*inv, z=dz*inv;
        sp[0]=w0;
        sp[1]=w1*x; sp[2]=w1*y; sp[3]=w1*z;
        sp[4]=wa*x*z; sp[5]=wa*x*y;
        sp[6]=wb*(y*y-0.5f*(x*x+z*z));
        sp[7]=wa*y*z; sp[8]=wc*(z*z-x*x);
      }
    }
    __syncthreads();
    int lim = min(64, u1-ib);
    for(int ii=0; ii<lim; ii++){
      const float* xr = xemb + (size_t)(ib+ii)*9*CCH + t;
      #pragma unroll
      for(int m=0;m<9;m++){
        float xv = xr[m*CCH];
        acc0 += ssh[ii][0][m]*xv;
        acc1 += ssh[ii][1][m]*xv;
        acc2 += ssh[ii][2][m]*xv;
        acc3 += ssh[ii][3][m]*xv;
      }
    }
  }
  g_kin[(j0+0)*CCH+t]=acc0;
  g_kin[(j0+1)*CCH+t]=acc1;
  g_kin[(j0+2)*CCH+t]=acc2;
  g_kin[(j0+3)*CCH+t]=acc3;
}

// ---------------- generic GEMM: Y[r,c] = bias[c] + sum_k X[r,k]*Wt[k,c] ----------------
// row r maps to global offset (r/m)*gs + (base + r%m)*C  (same layout for X and Y)
__global__ void __launch_bounds__(128) k_gemm(int xsel, int ysel, int widx,
                                              const float* __restrict__ Xext,
                                              const float* __restrict__ bias,
                                              int m, int gs, int base){
  const float* X = (xsel==0)?g_qin : (xsel==1)?g_kin : (xsel==2)?Xext : g_O1;
  float*       Y = (ysel==0)?g_q   : (ysel==1)?g_k   : (ysel==2)?g_V  : g_O2;
  const float* Wt = g_wt + (size_t)widx*CCH*CCH;
  const int t = threadIdx.x;
  __shared__ __align__(16) float xs[128*36];   // [k][r] with stride 36 (float4-aligned)
  const int r0 = blockIdx.x*32;
  for(int e=t; e<32*128; e+=128){
    int r = e>>7, k = e&127;
    int grow = r0 + r;
    int off = (grow/m)*gs + (base + grow%m)*CCH + k;
    xs[k*36+r] = X[off];
  }
  __syncthreads();
  float acc[32];
  float bv = bias ? bias[t] : 0.0f;
  #pragma unroll
  for(int r=0;r<32;r++) acc[r]=bv;
  #pragma unroll 4
  for(int k=0;k<128;k++){
    float wv = Wt[k*CCH + t];
    const float4* xp = reinterpret_cast<const float4*>(&xs[k*36]);
    #pragma unroll
    for(int rr=0;rr<8;rr++){
      float4 xv = xp[rr];
      acc[rr*4+0] += xv.x*wv;
      acc[rr*4+1] += xv.y*wv;
      acc[rr*4+2] += xv.z*wv;
      acc[rr*4+3] += xv.w*wv;
    }
  }
  #pragma unroll
  for(int r=0;r<32;r++){
    int grow = r0 + r;
    int off = (grow/m)*gs + (base + grow%m)*CCH + t;
    Y[off] = acc[r];
  }
}

// ---------------- attention: 4 nodes per block ----------------
__global__ void __launch_bounds__(128) k_attn(){
  const int i0 = blockIdx.x*4;
  const int t  = threadIdx.x;
  const int w  = t>>5, lane = t&31;
  __shared__ float sq[4][CCH];
  __shared__ float sp[4][8*MAXB];
  __shared__ int sbs[4], sbe[4];
  #pragma unroll
  for(int it=0; it<4; it++) sq[it][t] = g_q[(i0+it)*CCH + t];
  if(t<4){ sbs[t]=g_bs[i0+t]; sbe[t]=g_be[i0+t]; }
  __syncthreads();
  int u0 = min(min(sbs[0],sbs[1]),min(sbs[2],sbs[3]));
  int u1 = max(max(sbe[0],sbe[1]),max(sbe[2],sbe[3]));
  int un = u1-u0;
  // scores
  for(int e=t; e<4*8*un; e+=128){
    int it  = e/(8*un);
    int rem = e - it*8*un;
    int h   = rem/un;
    int jj  = rem - h*un;
    int j   = u0+jj;
    float s = -1e30f;
    if(j>=sbs[it] && j<sbe[it]){
      const float4* kv = reinterpret_cast<const float4*>(g_k + j*CCH + h*16);
      const float4* qv = reinterpret_cast<const float4*>(&sq[it][h*16]);
      float dot=0.0f;
      #pragma unroll
      for(int q4=0;q4<4;q4++){
        float4 a=qv[q4], b=kv[q4];
        dot += a.x*b.x + a.y*b.y + a.z*b.z + a.w*b.w;
      }
      s = dot*0.25f;   // D^-0.5 = 1/4
    }
    sp[it][h*un+jj] = s;
  }
  __syncthreads();
  // softmax: 32 (it,h) rows across 4 warps
  for(int row=w; row<32; row+=4){
    int it=row>>3, h=row&7;
    float* p = &sp[it][h*un];
    float mx=-1e30f;
    for(int jj=lane; jj<un; jj+=32) mx=fmaxf(mx,p[jj]);
    mx = wredmax(mx);
    float sm=0.0f;
    for(int jj=lane; jj<un; jj+=32){ float e=__expf(p[jj]-mx); p[jj]=e; sm+=e; }
    sm = wredsum(sm);
    float inv = 1.0f/sm;
    for(int jj=lane; jj<un; jj+=32) p[jj]*=inv;
  }
  __syncthreads();
  // output: thread t = channel c, h = c/16
  const int h = t>>4;
  float acc[4][9];
  #pragma unroll
  for(int it=0;it<4;it++)
    #pragma unroll
    for(int m=0;m<9;m++) acc[it][m]=0.0f;
  for(int jj=0; jj<un; jj++){
    const float* vr = g_V + (size_t)(u0+jj)*9*CCH + t;
    float p0=sp[0][h*un+jj], p1=sp[1][h*un+jj], p2=sp[2][h*un+jj], p3=sp[3][h*un+jj];
    #pragma unroll
    for(int m=0;m<9;m++){
      float v = vr[m*CCH];
      acc[0][m] += p0*v; acc[1][m] += p1*v; acc[2][m] += p2*v; acc[3][m] += p3*v;
    }
  }
  #pragma unroll
  for(int it=0;it<4;it++)
    #pragma unroll
    for(int m=0;m<9;m++)
      g_O1[((size_t)(i0+it)*9+m)*CCH + t] = acc[it][m];
}

// ---------------- residual + LayerNorm ----------------
__global__ void __launch_bounds__(256) k_ln(const float* __restrict__ xemb,
                                            const float* __restrict__ lng,
                                            const float* __restrict__ lnb,
                                            float* __restrict__ out){
  int row  = blockIdx.x*8 + (threadIdx.x>>5);
  int lane = threadIdx.x & 31;
  int m = row % 9;
  int l = (m==0) ? 0 : ((m<4) ? 1 : 2);
  const float* xr = xemb + (size_t)row*CCH;
  const float* orr = g_O2 + (size_t)row*CCH;
  float v[4]; float sum=0.0f;
  #pragma unroll
  for(int q=0;q<4;q++){ int c=lane+32*q; v[q]=xr[c]+orr[c]; sum+=v[q]; }
  sum = wredsum(sum);
  float mu = sum*(1.0f/CCH);
  float vs=0.0f;
  #pragma unroll
  for(int q=0;q<4;q++){ float d=v[q]-mu; vs+=d*d; }
  vs = wredsum(vs);
  float rs = rsqrtf(vs*(1.0f/CCH) + 1e-5f);
  #pragma unroll
  for(int q=0;q<4;q++){
    int c=lane+32*q;
    out[(size_t)row*CCH+c] = (v[q]-mu)*rs*lng[l*CCH+c] + lnb[l*CCH+c];
  }
}

// ---------------- launch ----------------
extern "C" void kernel_launch(void* const* d_in, const int* in_sizes, int n_in,
                              void* d_out, int out_size){
  const float* xemb = (const float*)d_in[0];
  const float* pos  = (const float*)d_in[1];
  const float* q_w  = (const float*)d_in[2];
  const float* q_b  = (const float*)d_in[3];
  const float* k_w  = (const float*)d_in[4];
  const float* k_b  = (const float*)d_in[5];
  const float* v_w  = (const float*)d_in[6];
  const float* v_b0 = (const float*)d_in[7];
  const float* out_w= (const float*)d_in[8];
  const float* ln_g = (const float*)d_in[9];
  const float* ln_b = (const float*)d_in[10];
  const int*   batw = (const int*)d_in[11];   // int32 or int64 words (auto-detected)
  float* out = (float*)d_out;

  k_batchrange<<<1, NN>>>(batw);
  k_transpose<<<128, dim3(32,8)>>>(q_w, k_w, v_w, out_w);
  k_qin<<<NN/8, 256>>>(pos, xemb);
  k_kin<<<NN/4, 128>>>(pos, xemb);
  // q / k projections
  k_gemm<<<NN/32, 128>>>(0, 0, 0, nullptr, q_b, 1, CCH, 0);
  k_gemm<<<NN/32, 128>>>(1, 1, 1, nullptr, k_b, 1, CCH, 0);
  // v projections per l
  k_gemm<<<(NN*1)/32, 128>>>(2, 2, 2, xemb, v_b0,   1, 9*CCH, 0);
  k_gemm<<<(NN*3)/32, 128>>>(2, 2, 3, xemb, nullptr, 3, 9*CCH, 1);
  k_gemm<<<(NN*5)/32, 128>>>(2, 2, 4, xemb, nullptr, 5, 9*CCH, 4);
  // attention + weighted V
  k_attn<<<NN/4, 128>>>();
  // output projections per l
  k_gemm<<<(NN*1)/32, 128>>>(3, 3, 5, nullptr, nullptr, 1, 9*CCH, 0);
  k_gemm<<<(NN*3)/32, 128>>>(3, 3, 6, nullptr, nullptr, 3, 9*CCH, 1);
  k_gemm<<<(NN*5)/32, 128>>>(3, 3, 7, nullptr, nullptr, 5, 9*CCH, 4);
  // residual + LN -> out
  k_ln<<<(NN*9)/8, 256>>>(xemb, ln_g, ln_b, out);
}

// round 2
// speedup vs baseline: 2.3969x; 2.3969x over previous
#include <cuda_runtime.h>

#define NN 1024
#define CCH 128
#define MAXB 320
#define NCHUNK 4

// ---------------- scratch (device globals; no allocation) ----------------
__device__ int   g_bs[NN], g_be[NN];
__device__ float g_qin[NN*CCH], g_kin[NN*CCH];
__device__ float g_q[NN*CCH],  g_k[NN*CCH];
__device__ float g_wt[8*CCH*CCH];      // transposed: 0 qw, 1 kw, 2-4 vw[l], 5-7 ow[l]
__device__ float g_V [NN*9*CCH];
__device__ float g_O1[NN*9*CCH];
__device__ float g_O2[NN*9*CCH];
__device__ float g_P [NN*8*MAXB];      // softmax probs, row-relative index

__device__ __forceinline__ float wredsum(float v){
  #pragma unroll
  for(int o=16;o;o>>=1) v += __shfl_xor_sync(0xffffffffu, v, o);
  return v;
}
__device__ __forceinline__ float wredmax(float v){
  #pragma unroll
  for(int o=16;o;o>>=1) v = fmaxf(v, __shfl_xor_sync(0xffffffffu, v, o));
  return v;
}

// SH constants
#define SH_C0 0.28209479177387814f
#define SH_C1 0.4886025119029199f
#define SH_S15 1.0925484305920792f
#define SH_S5 0.6307831305050401f

// ---------------- batch ranges (auto-detect int32 vs int64 batch) ----------------
__global__ void k_batchrange(const int* __restrict__ words){
  __shared__ int mono;
  __shared__ int sb[NN];
  int t = threadIdx.x;
  if(t==0) mono = 1;
  __syncthreads();
  if(t < NN-1 && words[t] > words[t+1]) atomicExch(&mono, 0);
  __syncthreads();
  int b = mono ? words[t] : words[2*t];
  sb[t] = b;
  __syncthreads();
  int lo=0, hi=NN;
  while(lo<hi){ int mid=(lo+hi)>>1; if(sb[mid] <  b) lo=mid+1; else hi=mid; }
  g_bs[t]=lo;
  lo=t; hi=NN;
  while(lo<hi){ int mid=(lo+hi)>>1; if(sb[mid] <= b) lo=mid+1; else hi=mid; }
  g_be[t]=lo;
}

__global__ void k_zero(){
  int idx = blockIdx.x*blockDim.x + threadIdx.x;
  reinterpret_cast<float4*>(g_kin)[idx] = make_float4(0.f,0.f,0.f,0.f);
}

// ---------------- weight transposes: g_wt[m][k*C+c] = W[c*C+k] ----------------
__global__ void k_transpose(const float* __restrict__ qw, const float* __restrict__ kw,
                            const float* __restrict__ vw, const float* __restrict__ ow){
  int mat  = blockIdx.x >> 4;
  int tile = blockIdx.x & 15;
  const float* src;
  if(mat==0) src=qw; else if(mat==1) src=kw;
  else if(mat<5) src=vw + (mat-2)*CCH*CCH;
  else src=ow + (mat-5)*CCH*CCH;
  float* dst = g_wt + mat*CCH*CCH;
  int tx=threadIdx.x, ty=threadIdx.y;
  int bx=(tile&3)*32, by=(tile>>2)*32;
  __shared__ float s[32][33];
  #pragma unroll
  for(int r=0;r<32;r+=8) s[ty+r][tx] = src[(by+ty+r)*CCH + bx+tx];
  __syncthreads();
  #pragma unroll
  for(int r=0;r<32;r+=8) dst[(bx+ty+r)*CCH + by+tx] = s[tx][ty+r];
}

// ---------------- q_in ----------------
__global__ void __launch_bounds__(256) k_qin(const float* __restrict__ pos,
                                             const float* __restrict__ xemb){
  int i    = blockIdx.x*8 + (threadIdx.x>>5);
  int lane = threadIdx.x & 31;
  float px=pos[i*3+0], py=pos[i*3+1], pz=pos[i*3+2];
  int bs=g_bs[i], be=g_be[i];
  float a0=0,a1=0,a2=0,a3=0,a4=0,a5=0,a6=0,a7=0,a8=0;
  for(int j=bs+lane; j<be; j+=32){
    if(j==i) continue;
    float dx=px-pos[j*3+0], dy=py-pos[j*3+1], dz=pz-pos[j*3+2];
    float d = fmaxf(sqrtf(dx*dx+dy*dy+dz*dz), 1e-8f);
    float inv = 1.0f/d;
    float x=dx*inv, y=dy*inv, z=dz*inv;
    a0 += 1.0f;
    a1 += x; a2 += y; a3 += z;
    a4 += x*z; a5 += x*y;
    a6 += y*y - 0.5f*(x*x+z*z);
    a7 += y*z; a8 += z*z - x*x;
  }
  a0=wredsum(a0); a1=wredsum(a1); a2=wredsum(a2); a3=wredsum(a3);
  a4=wredsum(a4); a5=wredsum(a5); a6=wredsum(a6); a7=wredsum(a7); a8=wredsum(a8);
  const float invN = 1.0f/(float)NN;
  float s0 = a0 * (SH_C0*invN);
  float w1 = SH_C1*invN/3.0f;
  float s1 = a1*w1, s2 = a2*w1, s3 = a3*w1;
  float wa = SH_S15*invN/5.0f, wb = SH_S5*invN/5.0f, wc = 0.5f*SH_S15*invN/5.0f;
  float s4 = a4*wa, s5 = a5*wa, s6 = a6*wb, s7 = a7*wa, s8 = a8*wc;
  const float* xr = xemb + (size_t)i*9*CCH;
  for(int c=lane; c<CCH; c+=32){
    float s = s0*xr[c]       + s1*xr[CCH+c]   + s2*xr[2*CCH+c]
            + s3*xr[3*CCH+c] + s4*xr[4*CCH+c] + s5*xr[5*CCH+c]
            + s6*xr[6*CCH+c] + s7*xr[7*CCH+c] + s8*xr[8*CCH+c];
    g_qin[i*CCH+c] = s;
  }
}

// ---------------- k_in: 8 j's per block, i-chunked, atomic accumulate ----------------
__global__ void __launch_bounds__(128) k_kin(const float* __restrict__ pos,
                                             const float* __restrict__ xemb){
  const int j0 = blockIdx.x*8;
  const int chunk = blockIdx.y;
  const int t  = threadIdx.x;
  __shared__ __align__(16) float ssh[16][8][12];
  __shared__ float spj[8][3];
  __shared__ int   sbsj[8];
  __shared__ int   sr[2];
  if(t<8){
    spj[t][0]=pos[(j0+t)*3+0]; spj[t][1]=pos[(j0+t)*3+1]; spj[t][2]=pos[(j0+t)*3+2];
    sbsj[t]=g_bs[j0+t];
  }
  if(t==0){
    int u0=g_bs[j0], u1=g_be[j0];
    #pragma unroll
    for(int q=1;q<8;q++){ u0=min(u0,g_bs[j0+q]); u1=max(u1,g_be[j0+q]); }
    sr[0]=u0; sr[1]=u1;
  }
  __syncthreads();
  const int u0=sr[0], un=sr[1]-sr[0];
  const int c0 = u0 + (un*chunk)/NCHUNK;
  const int c1 = u0 + (un*(chunk+1))/NCHUNK;
  const float invN = 1.0f/(float)NN;
  const float w0 = SH_C0*invN;
  const float w1 = SH_C1*invN/3.0f;
  const float wa = SH_S15*invN/5.0f, wb = SH_S5*invN/5.0f, wc = 0.5f*SH_S15*invN/5.0f;
  float acc[8]={0,0,0,0,0,0,0,0};
  for(int ib=c0; ib<c1; ib+=16){
    __syncthreads();
    {
      int ii=t>>3, jt=t&7;
      int i = ib+ii;
      float* sp = &ssh[ii][jt][0];
      bool ok = (i<c1) && (i != j0+jt) && (g_bs[i]==sbsj[jt]);
      if(!ok){
        #pragma unroll
        for(int m=0;m<9;m++) sp[m]=0.0f;
      } else {
        float dx=pos[i*3+0]-spj[jt][0];
        float dy=pos[i*3+1]-spj[jt][1];
        float dz=pos[i*3+2]-spj[jt][2];
        float d = fmaxf(sqrtf(dx*dx+dy*dy+dz*dz), 1e-8f);
        float inv = 1.0f/d;
        float x=dx*inv, y=dy*inv, z=dz*inv;
        sp[0]=w0;
        sp[1]=w1*x; sp[2]=w1*y; sp[3]=w1*z;
        sp[4]=wa*x*z; sp[5]=wa*x*y;
        sp[6]=wb*(y*y-0.5f*(x*x+z*z));
        sp[7]=wa*y*z; sp[8]=wc*(z*z-x*x);
      }
    }
    __syncthreads();
    int lim = min(16, c1-ib);
    for(int ii=0; ii<lim; ii++){
      const float* xr = xemb + (size_t)(ib+ii)*9*CCH + t;
      float xv[9];
      #pragma unroll
      for(int m=0;m<9;m++) xv[m]=xr[m*CCH];
      #pragma unroll
      for(int q=0;q<8;q++){
        const float4* shp = reinterpret_cast<const float4*>(&ssh[ii][q][0]);
        float4 a=shp[0], b=shp[1];
        float c8=ssh[ii][q][8];
        acc[q] += a.x*xv[0]+a.y*xv[1]+a.z*xv[2]+a.w*xv[3]
                + b.x*xv[4]+b.y*xv[5]+b.z*xv[6]+b.w*xv[7]+c8*xv[8];
      }
    }
  }
  #pragma unroll
  for(int q=0;q<8;q++) atomicAdd(&g_kin[(j0+q)*CCH+t], acc[q]);
}

// ---------------- fused GEMM: 8 rows/block ----------------
// mode 0: qk (rows 0..2047); mode 1: V proj (rows 0..9215); mode 2: out proj
__global__ void __launch_bounds__(128) k_gemm(int mode, const float* __restrict__ Xext,
                                              const float* __restrict__ qb,
                                              const float* __restrict__ kb,
                                              const float* __restrict__ vb0){
  const int r0 = blockIdx.x*8;
  const int t  = threadIdx.x;
  const float* X; float* Y; int widx; const float* bias=nullptr;
  int offs[8];
  if(mode==0){
    if(r0<1024){ X=g_qin; Y=g_q; widx=0; bias=qb; }
    else       { X=g_kin; Y=g_k; widx=1; bias=kb; }
    int base=(r0<1024)?r0:(r0-1024);
    #pragma unroll
    for(int rr=0;rr<8;rr++) offs[rr]=(base+rr)*CCH;
  } else {
    X = (mode==1)? Xext : g_O1;
    Y = (mode==1)? g_V  : g_O2;
    int wofs = (mode==1)?2:5;
    if(r0<1024){
      widx=wofs;
      if(mode==1) bias=vb0;
      #pragma unroll
      for(int rr=0;rr<8;rr++) offs[rr]=(r0+rr)*9*CCH;
    } else if(r0<4096){
      widx=wofs+1;
      int q0=r0-1024;
      #pragma unroll
      for(int rr=0;rr<8;rr++){ int q=q0+rr; offs[rr]=(q/3)*9*CCH + (1+q%3)*CCH; }
    } else {
      widx=wofs+2;
      int q0=r0-4096;
      #pragma unroll
      for(int rr=0;rr<8;rr++){ int q=q0+rr; offs[rr]=(q/5)*9*CCH + (4+q%5)*CCH; }
    }
  }
  __shared__ __align__(16) float xs[128*8];
  __shared__ int soffs[8];
  if(t<8) soffs[t]=offs[t];
  __syncthreads();
  #pragma unroll
  for(int q=0;q<8;q++){
    int e = t + q*128;
    int rr = e>>7, k = e&127;
    xs[k*8+rr] = X[soffs[rr]+k];
  }
  __syncthreads();
  const float* Wt = g_wt + (size_t)widx*CCH*CCH;
  float bv = bias ? bias[t] : 0.0f;
  float acc[8];
  #pragma unroll
  for(int rr=0;rr<8;rr++) acc[rr]=bv;
  #pragma unroll 4
  for(int k=0;k<128;k++){
    float wv = Wt[k*CCH + t];
    const float4* xp = reinterpret_cast<const float4*>(&xs[k*8]);
    float4 x0=xp[0], x1=xp[1];
    acc[0]+=x0.x*wv; acc[1]+=x0.y*wv; acc[2]+=x0.z*wv; acc[3]+=x0.w*wv;
    acc[4]+=x1.x*wv; acc[5]+=x1.y*wv; acc[6]+=x1.z*wv; acc[7]+=x1.w*wv;
  }
  #pragma unroll
  for(int rr=0;rr<8;rr++) Y[offs[rr]+t]=acc[rr];
}

// ---------------- scores + softmax -> g_P (row-relative) ----------------
__global__ void __launch_bounds__(128) k_score(){
  const int i0 = blockIdx.x*4;
  const int t  = threadIdx.x;
  const int w  = t>>5, lane = t&31;
  __shared__ float sq[4][CCH];
  __shared__ float sp[4][8][MAXB];
  __shared__ int sbs[4], sbe[4];
  #pragma unroll
  for(int it=0; it<4; it++) sq[it][t] = g_q[(i0+it)*CCH + t];
  if(t<4){ sbs[t]=g_bs[i0+t]; sbe[t]=g_be[i0+t]; }
  __syncthreads();
  #pragma unroll
  for(int it=0; it<4; it++){
    int bs=sbs[it], un=sbe[it]-bs;
    for(int e=t; e<8*un; e+=128){
      int h = e/un, jj = e-h*un;
      int j = bs+jj;
      const float4* kv = reinterpret_cast<const float4*>(g_k + j*CCH + h*16);
      const float4* qv = reinterpret_cast<const float4*>(&sq[it][h*16]);
      float dot=0.0f;
      #pragma unroll
      for(int q4=0;q4<4;q4++){
        float4 a=qv[q4], b=kv[q4];
        dot += a.x*b.x + a.y*b.y + a.z*b.z + a.w*b.w;
      }
      sp[it][h][jj] = dot*0.25f;
    }
  }
  __syncthreads();
  for(int row=w; row<32; row+=4){
    int it=row>>3, h=row&7;
    int un=sbe[it]-sbs[it];
    float* p = &sp[it][h][0];
    float mx=-1e30f;
    for(int jj=lane; jj<un; jj+=32) mx=fmaxf(mx,p[jj]);
    mx = wredmax(mx);
    float sm=0.0f;
    for(int jj=lane; jj<un; jj+=32){ float e=__expf(p[jj]-mx); p[jj]=e; sm+=e; }
    sm = wredsum(sm);
    float inv = 1.0f/sm;
    for(int jj=lane; jj<un; jj+=32) p[jj]*=inv;
  }
  __syncthreads();
  #pragma unroll
  for(int it=0; it<4; it++){
    int un=sbe[it]-sbs[it];
    for(int e=t; e<8*un; e+=128){
      int h = e/un, jj = e-h*un;
      g_P[((size_t)(i0+it)*8+h)*MAXB + jj] = sp[it][h][jj];
    }
  }
}

// ---------------- weighted V: 8 i's x 3 m's per block ----------------
__global__ void __launch_bounds__(128) k_wv(){
  const int i0 = blockIdx.x*8;
  const int mc = blockIdx.y*3;
  const int t  = threadIdx.x;
  const int h  = t>>4;
  __shared__ float ssp[8][8][33];
  __shared__ int sbs[8], sbe[8];
  __shared__ int sr[2];
  if(t<8){ sbs[t]=g_bs[i0+t]; sbe[t]=g_be[i0+t]; }
  __syncthreads();
  if(t==0){
    int u0=sbs[0], u1=sbe[0];
    #pragma unroll
    for(int q=1;q<8;q++){ u0=min(u0,sbs[q]); u1=max(u1,sbe[q]); }
    sr[0]=u0; sr[1]=u1;
  }
  __syncthreads();
  const int u0=sr[0], u1=sr[1];
  float acc[8][3];
  #pragma unroll
  for(int it=0;it<8;it++){ acc[it][0]=0; acc[it][1]=0; acc[it][2]=0; }
  for(int jt=u0; jt<u1; jt+=32){
    __syncthreads();
    #pragma unroll
    for(int q=0;q<16;q++){
      int e = t + q*128;
      int it = e>>8, hh=(e>>5)&7, jl=e&31;
      int j = jt+jl;
      float p = 0.0f;
      int rel = j - sbs[it];
      if(j<u1 && rel>=0 && j<sbe[it])
        p = g_P[((size_t)(i0+it)*8+hh)*MAXB + rel];
      ssp[it][hh][jl]=p;
    }
    __syncthreads();
    int lim = min(32, u1-jt);
    for(int jl=0; jl<lim; jl++){
      const float* vr = g_V + (size_t)(jt+jl)*9*CCH + mc*CCH + t;
      float v0=vr[0], v1=vr[CCH], v2=vr[2*CCH];
      #pragma unroll
      for(int it=0;it<8;it++){
        float p = ssp[it][h][jl];
        acc[it][0]+=p*v0; acc[it][1]+=p*v1; acc[it][2]+=p*v2;
      }
    }
  }
  #pragma unroll
  for(int it=0;it<8;it++)
    #pragma unroll
    for(int mm=0;mm<3;mm++)
      g_O1[((size_t)(i0+it)*9 + mc+mm)*CCH + t] = acc[it][mm];
}

// ---------------- residual + LayerNorm ----------------
__global__ void __launch_bounds__(256) k_ln(const float* __restrict__ xemb,
                                            const float* __restrict__ lng,
                                            const float* __restrict__ lnb,
                                            float* __restrict__ out){
  int row  = blockIdx.x*8 + (threadIdx.x>>5);
  int lane = threadIdx.x & 31;
  int m = row % 9;
  int l = (m==0) ? 0 : ((m<4) ? 1 : 2);
  const float* xr = xemb + (size_t)row*CCH;
  const float* orr = g_O2 + (size_t)row*CCH;
  float v[4]; float sum=0.0f;
  #pragma unroll
  for(int q=0;q<4;q++){ int c=lane+32*q; v[q]=xr[c]+orr[c]; sum+=v[q]; }
  sum = wredsum(sum);
  float mu = sum*(1.0f/CCH);
  float vs=0.0f;
  #pragma unroll
  for(int q=0;q<4;q++){ float d=v[q]-mu; vs+=d*d; }
  vs = wredsum(vs);
  float rs = rsqrtf(vs*(1.0f/CCH) + 1e-5f);
  #pragma unroll
  for(int q=0;q<4;q++){
    int c=lane+32*q;
    out[(size_t)row*CCH+c] = (v[q]-mu)*rs*lng[l*CCH+c] + lnb[l*CCH+c];
  }
}

// ---------------- launch ----------------
extern "C" void kernel_launch(void* const* d_in, const int* in_sizes, int n_in,
                              void* d_out, int out_size){
  const float* xemb = (const float*)d_in[0];
  const float* pos  = (const float*)d_in[1];
  const float* q_w  = (const float*)d_in[2];
  const float* q_b  = (const float*)d_in[3];
  const float* k_w  = (const float*)d_in[4];
  const float* k_b  = (const float*)d_in[5];
  const float* v_w  = (const float*)d_in[6];
  const float* v_b0 = (const float*)d_in[7];
  const float* out_w= (const float*)d_in[8];
  const float* ln_g = (const float*)d_in[9];
  const float* ln_b = (const float*)d_in[10];
  const int*   batw = (const int*)d_in[11];
  float* out = (float*)d_out;

  k_batchrange<<<1, NN>>>(batw);
  k_zero<<<64, 512>>>();
  k_transpose<<<128, dim3(32,8)>>>(q_w, k_w, v_w, out_w);
  k_qin<<<NN/8, 256>>>(pos, xemb);
  k_kin<<<dim3(NN/8, NCHUNK), 128>>>(pos, xemb);
  k_gemm<<<256, 128>>>(0, nullptr, q_b, k_b, nullptr);            // q,k proj
  k_gemm<<<1152, 128>>>(1, xemb, nullptr, nullptr, v_b0);         // V proj
  k_score<<<NN/4, 128>>>();
  k_wv<<<dim3(NN/8, 3), 128>>>();
  k_gemm<<<1152, 128>>>(2, nullptr, nullptr, nullptr, nullptr);   // out proj
  k_ln<<<(NN*9)/8, 256>>>(xemb, ln_g, ln_b, out);
}